// round 13
// baseline (speedup 1.0000x reference)
#include <cuda_runtime.h>
#include <cuda_bf16.h>

// ESN: T=2048 steps, N=2048 reservoir, D=128 input.
// out[t] = erf(U[t] + W_res @ out[t-1]) * 1/sqrt(N),  U = input @ W_in^T
#define T_STEPS 2048
#define N_RES   2048
#define D_IN    128
#define GBLK    128          // persistent blocks (1 per SM, all co-resident)
#define ROWS_PER_BLK 16      // N_RES / GBLK
#define NTHREADS 256
#define CPT      8           // columns per thread = N_RES / NTHREADS
#define NPAIR    8           // row pairs per block (f32x2 packs 2 rows)
#define INV_SQRT_N 0.022097086912079612f

__device__ float    g_U[T_STEPS * N_RES];   // input projection scratch (16 MB)
__device__ unsigned g_scount;               // accumulating step counter (never reset)
__device__ unsigned g_count;                // init-barrier arrive counter
__device__ unsigned g_epoch;                // init-barrier epoch (monotonic across runs)

typedef unsigned long long u64;

__device__ __forceinline__ u64 pack2(float lo, float hi) {
    u64 r; asm("mov.b64 %0, {%1,%2};" : "=l"(r) : "f"(lo), "f"(hi)); return r;
}
__device__ __forceinline__ void unpack2(u64 v, float& lo, float& hi) {
    asm("mov.b64 {%0,%1}, %2;" : "=f"(lo), "=f"(hi) : "l"(v));
}
__device__ __forceinline__ void fma2(u64& acc, u64 a, u64 b) {
    asm("fma.rn.f32x2 %0, %1, %2, %0;" : "+l"(acc) : "l"(a), "l"(b));
}
__device__ __forceinline__ u64 add2(u64 a, u64 b) {
    u64 r; asm("add.rn.f32x2 %0, %1, %2;" : "=l"(r) : "l"(a), "l"(b)); return r;
}
__device__ __forceinline__ u64 shfl_xor64(u64 v, int m) {
    unsigned lo = (unsigned)v, hi = (unsigned)(v >> 32);
    lo = __shfl_xor_sync(0xffffffffu, lo, m);
    hi = __shfl_xor_sync(0xffffffffu, hi, m);
    return ((u64)hi << 32) | (u64)lo;
}
__device__ __forceinline__ unsigned ldrelax(const unsigned* p) {
    unsigned v;
    asm volatile("ld.relaxed.gpu.global.u32 %0, [%1];" : "=r"(v) : "l"(p) : "memory");
    return v;
}

// One-time grid barrier at kernel start (epoch + counter-base agreement).
__device__ __forceinline__ void grid_barrier(int tid, unsigned target) {
    __syncthreads();
    if (tid == 0) {
        unsigned prev;
        asm volatile("atom.release.gpu.global.add.u32 %0, [%1], %2;"
                     : "=r"(prev) : "l"(&g_count), "r"(1u) : "memory");
        if (prev == (unsigned)(GBLK - 1)) {
            asm volatile("st.relaxed.gpu.global.u32 [%0], %1;"
                         :: "l"(&g_count), "r"(0u) : "memory");
            asm volatile("st.release.gpu.global.u32 [%0], %1;"
                         :: "l"(&g_epoch), "r"(target) : "memory");
        } else {
            unsigned cur;
            do {
                asm volatile("ld.acquire.gpu.global.u32 %0, [%1];"
                             : "=r"(cur) : "l"(&g_epoch) : "memory");
            } while (cur != target);
        }
    }
    __syncthreads();
}

// ---------------------------------------------------------------------------
// Kernel 1: U[t][n] = sum_d input[t][d] * W_in[n][d]   (2048 x 2048 x 128)
// ---------------------------------------------------------------------------
__global__ void __launch_bounds__(256) u_gemm_kernel(
    const float* __restrict__ inp, const float* __restrict__ win)
{
    __shared__ float As[32][129];
    __shared__ float Bs[32][129];
    const int tid = threadIdx.x;
    const int t0 = blockIdx.y * 32;
    const int n0 = blockIdx.x * 32;

    #pragma unroll
    for (int i = 0; i < 4; i++) {
        int f   = tid + i * 256;
        int row = f >> 5;
        int c4  = (f & 31) << 2;
        float4 va = *(const float4*)(inp + (t0 + row) * D_IN + c4);
        float4 vb = *(const float4*)(win + (n0 + row) * D_IN + c4);
        As[row][c4] = va.x; As[row][c4 + 1] = va.y; As[row][c4 + 2] = va.z; As[row][c4 + 3] = va.w;
        Bs[row][c4] = vb.x; Bs[row][c4 + 1] = vb.y; Bs[row][c4 + 2] = vb.z; Bs[row][c4 + 3] = vb.w;
    }
    __syncthreads();

    const int tx = tid & 15, ty = tid >> 4;
    float a00 = 0.f, a01 = 0.f, a10 = 0.f, a11 = 0.f;
    #pragma unroll 16
    for (int k = 0; k < D_IN; k++) {
        float x0 = As[2 * ty][k],     x1 = As[2 * ty + 1][k];
        float y0 = Bs[2 * tx][k],     y1 = Bs[2 * tx + 1][k];
        a00 = fmaf(x0, y0, a00); a01 = fmaf(x0, y1, a01);
        a10 = fmaf(x1, y0, a10); a11 = fmaf(x1, y1, a11);
    }
    const int r = t0 + 2 * ty, c = n0 + 2 * tx;
    g_U[r * N_RES + c]           = a00;
    g_U[r * N_RES + c + 1]       = a01;
    g_U[(r + 1) * N_RES + c]     = a10;
    g_U[(r + 1) * N_RES + c + 1] = a11;
}

// ---------------------------------------------------------------------------
// Kernel 2: persistent recurrence == R8's proven kernel with ONE change:
// the tid0 poll uses an 8-deep software-pipelined ld.relaxed probe (8 loads
// in flight; retire-one/issue-one => counter sampled every ~RT/8 instead of
// once per round trip), followed by fence.acq_rel.gpu on success.
// HB chain: producer STG -> bar -> red.release.gpu -> relaxed load observes
// -> fence.acquire -> bar.sync -> consumer loads.   (fence-based sync; all
// ops morally strong.)
// Topology invariants (measured R7/R9/R11/R12): 128 arrivals/step,
// 128 pollers chip-wide, everyone else parked at bar.sync.
// ---------------------------------------------------------------------------
__global__ void __launch_bounds__(NTHREADS, 1) esn_recur_kernel(
    const float* __restrict__ wres, float* __restrict__ out)
{
    __shared__ u64 red[NPAIR * NTHREADS];   // 16 KB reduction staging
    __shared__ unsigned s_cbase;

    const int tid = threadIdx.x;
    const int bid = blockIdx.x;
    const int r0  = bid * ROWS_PER_BLK;
    const int c0  = tid * CPT;
    const int wp  = tid >> 5, ln = tid & 31;

    // Load W_res slice: w[p][c] = {W[r0+2p][c0+c], W[r0+2p+1][c0+c]}
    u64 w[NPAIR][CPT];
    #pragma unroll
    for (int p = 0; p < NPAIR; p++) {
        const float4* ra = (const float4*)(wres + (r0 + 2 * p)     * N_RES + c0);
        const float4* rb = (const float4*)(wres + (r0 + 2 * p + 1) * N_RES + c0);
        float4 a0 = ra[0], a1 = ra[1];
        float4 b0 = rb[0], b1 = rb[1];
        w[p][0] = pack2(a0.x, b0.x); w[p][1] = pack2(a0.y, b0.y);
        w[p][2] = pack2(a0.z, b0.z); w[p][3] = pack2(a0.w, b0.w);
        w[p][4] = pack2(a1.x, b1.x); w[p][5] = pack2(a1.y, b1.y);
        w[p][6] = pack2(a1.z, b1.z); w[p][7] = pack2(a1.w, b1.w);
    }

    // Snapshot the quiescent step-counter; init barrier ensures agreement
    // before any arrival.
    if (tid == 0) {
        unsigned c;
        asm volatile("ld.relaxed.gpu.global.u32 %0, [%1];" : "=r"(c) : "l"(&g_scount) : "memory");
        s_cbase = c;
    }
    unsigned e0;
    asm volatile("ld.acquire.gpu.global.u32 %0, [%1];" : "=r"(e0) : "l"(&g_epoch) : "memory");
    grid_barrier(tid, e0 + 1);
    const unsigned cbase = s_cbase;

    // Step 0: x0 = erf(U[0]) * inv_sqrt_n ; then arrive.
    if (tid < ROWS_PER_BLK)
        out[r0 + tid] = erff(g_U[r0 + tid]) * INV_SQRT_N;
    __syncthreads();   // out stores happen-before tid0's release-arrival
    if (tid == 0)
        asm volatile("red.release.gpu.global.add.u32 [%0], %1;"
                     :: "l"(&g_scount), "r"(1u) : "memory");

    #pragma unroll 1
    for (int t = 1; t < T_STEPS; t++) {
        // Prefetch U[t] for my row (lanes 0/1 of each warp) before the wait.
        float u = 0.f;
        if (ln < 2) u = __ldg(&g_U[t * N_RES + r0 + 2 * wp + ln]);

        // Pipelined-probe barrier wait: 8 relaxed loads in flight, retire one
        // and issue one per iteration -> sampling interval ~RT/8. Counter is
        // monotonic so any sample >= tgt proves arrival.
        if (tid == 0) {
            const unsigned tgt = cbase + (unsigned)(GBLK * t);
            unsigned p0 = ldrelax(&g_scount), p1 = ldrelax(&g_scount);
            unsigned p2 = ldrelax(&g_scount), p3 = ldrelax(&g_scount);
            unsigned p4 = ldrelax(&g_scount), p5 = ldrelax(&g_scount);
            unsigned p6 = ldrelax(&g_scount), p7 = ldrelax(&g_scount);
            while ((int)(p0 - tgt) < 0) {
                p0 = p1; p1 = p2; p2 = p3; p3 = p4;
                p4 = p5; p5 = p6; p6 = p7; p7 = ldrelax(&g_scount);
            }
            asm volatile("fence.acq_rel.gpu;" ::: "memory");
        }
        __syncthreads();   // fence happens-before all lanes' loads

        // Load my 8 x values from the previous out row (L1 bypass: remote SMs).
        const float4* xp = (const float4*)(out + (t - 1) * N_RES + c0);
        float4 xv0 = __ldcg(xp);
        float4 xv1 = __ldcg(xp + 1);
        u64 xx[CPT];
        xx[0] = pack2(xv0.x, xv0.x); xx[1] = pack2(xv0.y, xv0.y);
        xx[2] = pack2(xv0.z, xv0.z); xx[3] = pack2(xv0.w, xv0.w);
        xx[4] = pack2(xv1.x, xv1.x); xx[5] = pack2(xv1.y, xv1.y);
        xx[6] = pack2(xv1.z, xv1.z); xx[7] = pack2(xv1.w, xv1.w);

        u64 acc[NPAIR];
        #pragma unroll
        for (int p = 0; p < NPAIR; p++) acc[p] = 0ULL;
        #pragma unroll
        for (int c = 0; c < CPT; c++) {
            #pragma unroll
            for (int p = 0; p < NPAIR; p++) fma2(acc[p], w[p][c], xx[c]);
        }

        // Stage partials; warp wp reduces row-pair wp across 256 threads.
        #pragma unroll
        for (int p = 0; p < NPAIR; p++) red[p * NTHREADS + tid] = acc[p];
        __syncthreads();

        u64 s = red[wp * NTHREADS + ln];
        #pragma unroll
        for (int k = 1; k < 8; k++) s = add2(s, red[wp * NTHREADS + ln + 32 * k]);
        #pragma unroll
        for (int m = 16; m >= 1; m >>= 1) s = add2(s, shfl_xor64(s, m));
        // Every lane now holds the full {row 2wp, row 2wp+1} dot-product pair.

        // Lanes 0/1 each finish one row: erf + out store (parallel erfs).
        if (ln < 2) {
            float lo, hi; unpack2(s, lo, hi);
            float pre = u + (ln == 0 ? lo : hi);
            out[t * N_RES + r0 + 2 * wp + ln] = erff(pre) * INV_SQRT_N;
        }
        __syncthreads();   // out stores done + red[] safe; HB to tid0 arrival

        if (tid == 0)
            asm volatile("red.release.gpu.global.add.u32 [%0], %1;"
                         :: "l"(&g_scount), "r"(1u) : "memory");
    }
}

// ---------------------------------------------------------------------------
extern "C" void kernel_launch(void* const* d_in, const int* in_sizes, int n_in,
                              void* d_out, int out_size)
{
    const float* input = (const float*)d_in[0];   // (2048, 128)
    const float* w_in  = (const float*)d_in[1];   // (2048, 128)
    const float* w_res = (const float*)d_in[2];   // (2048, 2048)
    float* out = (float*)d_out;                   // (2048, 2048)

    u_gemm_kernel<<<dim3(N_RES / 32, T_STEPS / 32), 256>>>(input, w_in);
    esn_recur_kernel<<<GBLK, NTHREADS>>>(w_res, out);
}

// round 14
// speedup vs baseline: 1.8298x; 1.8298x over previous
#include <cuda_runtime.h>
#include <cuda_bf16.h>

// ESN: T=2048 steps, N=2048 reservoir, D=128 input.
// out[t] = erf(U[t] + W_res @ out[t-1]) * 1/sqrt(N),  U = input @ W_in^T
#define T_STEPS 2048
#define N_RES   2048
#define D_IN    128
#define GBLK    128          // persistent blocks (1 per SM, all co-resident)
#define ROWS_PER_BLK 16      // N_RES / GBLK
#define NTHREADS 256
#define CPT      8           // columns per thread = N_RES / NTHREADS
#define NPAIR    8           // row pairs per block (f32x2 packs 2 rows)
#define NCOPY    8           // x-row replication factor (16 consumer blocks/copy)
#define INV_SQRT_N 0.022097086912079612f

__device__ float    g_U[T_STEPS * N_RES];        // input projection scratch (16 MB)
__device__ float    g_x8[2 * NCOPY * N_RES];     // replicated x rows, parity slots
__device__ unsigned g_scount;                    // accumulating step counter
__device__ unsigned g_count;                     // init-barrier arrive counter
__device__ unsigned g_epoch;                     // init-barrier epoch (monotonic)

typedef unsigned long long u64;

__device__ __forceinline__ u64 pack2(float lo, float hi) {
    u64 r; asm("mov.b64 %0, {%1,%2};" : "=l"(r) : "f"(lo), "f"(hi)); return r;
}
__device__ __forceinline__ void unpack2(u64 v, float& lo, float& hi) {
    asm("mov.b64 {%0,%1}, %2;" : "=f"(lo), "=f"(hi) : "l"(v));
}
__device__ __forceinline__ void fma2(u64& acc, u64 a, u64 b) {
    asm("fma.rn.f32x2 %0, %1, %2, %0;" : "+l"(acc) : "l"(a), "l"(b));
}
__device__ __forceinline__ u64 add2(u64 a, u64 b) {
    u64 r; asm("add.rn.f32x2 %0, %1, %2;" : "=l"(r) : "l"(a), "l"(b)); return r;
}
__device__ __forceinline__ u64 shfl_xor64(u64 v, int m) {
    unsigned lo = (unsigned)v, hi = (unsigned)(v >> 32);
    lo = __shfl_xor_sync(0xffffffffu, lo, m);
    hi = __shfl_xor_sync(0xffffffffu, hi, m);
    return ((u64)hi << 32) | (u64)lo;
}

// One-time grid barrier at kernel start (epoch + counter-base agreement).
__device__ __forceinline__ void grid_barrier(int tid, unsigned target) {
    __syncthreads();
    if (tid == 0) {
        unsigned prev;
        asm volatile("atom.release.gpu.global.add.u32 %0, [%1], %2;"
                     : "=r"(prev) : "l"(&g_count), "r"(1u) : "memory");
        if (prev == (unsigned)(GBLK - 1)) {
            asm volatile("st.relaxed.gpu.global.u32 [%0], %1;"
                         :: "l"(&g_count), "r"(0u) : "memory");
            asm volatile("st.release.gpu.global.u32 [%0], %1;"
                         :: "l"(&g_epoch), "r"(target) : "memory");
        } else {
            unsigned cur;
            do {
                asm volatile("ld.acquire.gpu.global.u32 %0, [%1];"
                             : "=r"(cur) : "l"(&g_epoch) : "memory");
            } while (cur != target);
        }
    }
    __syncthreads();
}

// ---------------------------------------------------------------------------
// Kernel 1: U[t][n] = sum_d input[t][d] * W_in[n][d]   (2048 x 2048 x 128)
// 64x64 output tile, 4x4 register micro-tile, K chunked 2x64, transposed smem.
// ---------------------------------------------------------------------------
__global__ void __launch_bounds__(256) u_gemm_kernel(
    const float* __restrict__ inp, const float* __restrict__ win)
{
    __shared__ float As[64][68];   // As[k][m] = inp[t0+m][kc+k]
    __shared__ float Bs[64][68];   // Bs[k][n] = win[n0+n][kc+k]
    const int tid = threadIdx.x;
    const int t0 = blockIdx.y * 64;
    const int n0 = blockIdx.x * 64;
    const int tx = tid & 15, ty = tid >> 4;

    float acc[4][4] = {};

    #pragma unroll
    for (int kc = 0; kc < D_IN; kc += 64) {
        __syncthreads();   // protect smem from previous chunk's readers
        #pragma unroll
        for (int i = 0; i < 4; i++) {
            int fi = tid + i * 256;       // 0..1023 float4 slots
            int m  = fi >> 4;             // 0..63
            int k4 = (fi & 15) << 2;      // 0..60
            float4 va = *(const float4*)(inp + (t0 + m) * D_IN + kc + k4);
            As[k4][m] = va.x; As[k4 + 1][m] = va.y; As[k4 + 2][m] = va.z; As[k4 + 3][m] = va.w;
            float4 vb = *(const float4*)(win + (n0 + m) * D_IN + kc + k4);
            Bs[k4][m] = vb.x; Bs[k4 + 1][m] = vb.y; Bs[k4 + 2][m] = vb.z; Bs[k4 + 3][m] = vb.w;
        }
        __syncthreads();

        #pragma unroll 16
        for (int k = 0; k < 64; k++) {
            float4 a = *(const float4*)(&As[k][4 * ty]);
            float4 b = *(const float4*)(&Bs[k][4 * tx]);
            acc[0][0] = fmaf(a.x, b.x, acc[0][0]); acc[0][1] = fmaf(a.x, b.y, acc[0][1]);
            acc[0][2] = fmaf(a.x, b.z, acc[0][2]); acc[0][3] = fmaf(a.x, b.w, acc[0][3]);
            acc[1][0] = fmaf(a.y, b.x, acc[1][0]); acc[1][1] = fmaf(a.y, b.y, acc[1][1]);
            acc[1][2] = fmaf(a.y, b.z, acc[1][2]); acc[1][3] = fmaf(a.y, b.w, acc[1][3]);
            acc[2][0] = fmaf(a.z, b.x, acc[2][0]); acc[2][1] = fmaf(a.z, b.y, acc[2][1]);
            acc[2][2] = fmaf(a.z, b.z, acc[2][2]); acc[2][3] = fmaf(a.z, b.w, acc[2][3]);
            acc[3][0] = fmaf(a.w, b.x, acc[3][0]); acc[3][1] = fmaf(a.w, b.y, acc[3][1]);
            acc[3][2] = fmaf(a.w, b.z, acc[3][2]); acc[3][3] = fmaf(a.w, b.w, acc[3][3]);
        }
    }

    #pragma unroll
    for (int i = 0; i < 4; i++) {
        float4 v = make_float4(acc[i][0], acc[i][1], acc[i][2], acc[i][3]);
        *(float4*)(g_U + (t0 + 4 * ty + i) * N_RES + n0 + 4 * tx) = v;
    }
}

// ---------------------------------------------------------------------------
// Kernel 2: persistent recurrence == R8's proven kernel + 8-way replicated
// x staging. Producer warps store their {v0,v1} pair into 8 copies of the x
// row (parity double buffer) — fire-and-forget stores, off the critical path.
// Consumer block b reads copy b>>4: per-L2-line request count drops 128->16,
// cutting the post-barrier read storm ~500 -> ~70 cyc.
// Depth-2 slot safety: slot t&1 is rewritten at step t only after the counter
// proves all blocks published t-1 => all finished reading t-2 from that slot.
// Sync topology is EXACTLY R8 (128 arrivals/step, 128 acquire-spin pollers,
// everyone else parked at bar.sync) — measured optimal across R7..R13.
// ---------------------------------------------------------------------------
__global__ void __launch_bounds__(NTHREADS, 1) esn_recur_kernel(
    const float* __restrict__ wres, float* __restrict__ out)
{
    __shared__ u64 red[NPAIR * NTHREADS];   // 16 KB reduction staging
    __shared__ unsigned s_cbase;

    const int tid = threadIdx.x;
    const int bid = blockIdx.x;
    const int r0  = bid * ROWS_PER_BLK;
    const int c0  = tid * CPT;
    const int wp  = tid >> 5, ln = tid & 31;
    const int mycopy = bid >> 4;            // 16 blocks share each copy

    // Load W_res slice: w[p][c] = {W[r0+2p][c0+c], W[r0+2p+1][c0+c]}
    u64 w[NPAIR][CPT];
    #pragma unroll
    for (int p = 0; p < NPAIR; p++) {
        const float4* ra = (const float4*)(wres + (r0 + 2 * p)     * N_RES + c0);
        const float4* rb = (const float4*)(wres + (r0 + 2 * p + 1) * N_RES + c0);
        float4 a0 = ra[0], a1 = ra[1];
        float4 b0 = rb[0], b1 = rb[1];
        w[p][0] = pack2(a0.x, b0.x); w[p][1] = pack2(a0.y, b0.y);
        w[p][2] = pack2(a0.z, b0.z); w[p][3] = pack2(a0.w, b0.w);
        w[p][4] = pack2(a1.x, b1.x); w[p][5] = pack2(a1.y, b1.y);
        w[p][6] = pack2(a1.z, b1.z); w[p][7] = pack2(a1.w, b1.w);
    }

    // Snapshot the quiescent step-counter; init barrier ensures agreement
    // before any arrival.
    if (tid == 0) {
        unsigned c;
        asm volatile("ld.relaxed.gpu.global.u32 %0, [%1];" : "=r"(c) : "l"(&g_scount) : "memory");
        s_cbase = c;
    }
    unsigned e0;
    asm volatile("ld.acquire.gpu.global.u32 %0, [%1];" : "=r"(e0) : "l"(&g_epoch) : "memory");
    grid_barrier(tid, e0 + 1);
    const unsigned cbase = s_cbase;

    // Step 0: warp wp handles rows 2wp,2wp+1; publish out + all 8 copies.
    {
        float v = 0.f;
        if (ln < 2) {
            const int r = r0 + 2 * wp + ln;
            v = erff(g_U[r]) * INV_SQRT_N;
        }
        float v0 = __shfl_sync(0xffffffffu, v, 0);
        float v1 = __shfl_sync(0xffffffffu, v, 1);
        u64 pair = pack2(v0, v1);
        if (ln == 0)
            *(u64*)(out + r0 + 2 * wp) = pair;
        if (ln < NCOPY)
            *(u64*)(g_x8 + ln * N_RES + r0 + 2 * wp) = pair;   // slot 0
    }
    __syncthreads();   // all stores happen-before tid0's release-arrival
    if (tid == 0)
        asm volatile("red.release.gpu.global.add.u32 [%0], %1;"
                     :: "l"(&g_scount), "r"(1u) : "memory");

    #pragma unroll 1
    for (int t = 1; t < T_STEPS; t++) {
        // Prefetch U[t] for my row (lanes 0/1 of each warp) before the wait.
        float u = 0.f;
        if (ln < 2) u = __ldg(&g_U[t * N_RES + r0 + 2 * wp + ln]);

        // R8's proven barrier wait: tid0 acquire-spin, bar broadcasts.
        if (tid == 0) {
            const unsigned tgt = cbase + (unsigned)(GBLK * t);
            unsigned cur;
            do {
                asm volatile("ld.acquire.gpu.global.u32 %0, [%1];"
                             : "=r"(cur) : "l"(&g_scount) : "memory");
            } while ((int)(cur - tgt) < 0);
        }
        __syncthreads();   // acquire happens-before all lanes' loads

        // Load my 8 x values from MY copy of the previous x row (L1 bypass).
        const float4* xp = (const float4*)(g_x8 + ((t - 1) & 1) * (NCOPY * N_RES)
                                                + mycopy * N_RES + c0);
        float4 xv0 = __ldcg(xp);
        float4 xv1 = __ldcg(xp + 1);
        u64 xx[CPT];
        xx[0] = pack2(xv0.x, xv0.x); xx[1] = pack2(xv0.y, xv0.y);
        xx[2] = pack2(xv0.z, xv0.z); xx[3] = pack2(xv0.w, xv0.w);
        xx[4] = pack2(xv1.x, xv1.x); xx[5] = pack2(xv1.y, xv1.y);
        xx[6] = pack2(xv1.z, xv1.z); xx[7] = pack2(xv1.w, xv1.w);

        u64 acc[NPAIR];
        #pragma unroll
        for (int p = 0; p < NPAIR; p++) acc[p] = 0ULL;
        #pragma unroll
        for (int c = 0; c < CPT; c++) {
            #pragma unroll
            for (int p = 0; p < NPAIR; p++) fma2(acc[p], w[p][c], xx[c]);
        }

        // Stage partials; warp wp reduces row-pair wp across 256 threads.
        #pragma unroll
        for (int p = 0; p < NPAIR; p++) red[p * NTHREADS + tid] = acc[p];
        __syncthreads();

        u64 s = red[wp * NTHREADS + ln];
        #pragma unroll
        for (int k = 1; k < 8; k++) s = add2(s, red[wp * NTHREADS + ln + 32 * k]);
        #pragma unroll
        for (int m = 16; m >= 1; m >>= 1) s = add2(s, shfl_xor64(s, m));
        // Every lane now holds the full {row 2wp, row 2wp+1} dot-product pair.

        // Lanes 0/1 run the two erfs in parallel; broadcast; publish.
        float v = 0.f;
        if (ln < 2) {
            float lo, hi; unpack2(s, lo, hi);
            v = erff(u + (ln == 0 ? lo : hi)) * INV_SQRT_N;
        }
        float v0 = __shfl_sync(0xffffffffu, v, 0);
        float v1 = __shfl_sync(0xffffffffu, v, 1);
        u64 pair = pack2(v0, v1);
        if (ln == 0)
            *(u64*)(out + t * N_RES + r0 + 2 * wp) = pair;
        if (ln < NCOPY)
            *(u64*)(g_x8 + (t & 1) * (NCOPY * N_RES) + ln * N_RES + r0 + 2 * wp) = pair;
        __syncthreads();   // all stores done + red[] safe; HB to tid0 arrival

        if (tid == 0)
            asm volatile("red.release.gpu.global.add.u32 [%0], %1;"
                         :: "l"(&g_scount), "r"(1u) : "memory");
    }
}

// ---------------------------------------------------------------------------
extern "C" void kernel_launch(void* const* d_in, const int* in_sizes, int n_in,
                              void* d_out, int out_size)
{
    const float* input = (const float*)d_in[0];   // (2048, 128)
    const float* w_in  = (const float*)d_in[1];   // (2048, 128)
    const float* w_res = (const float*)d_in[2];   // (2048, 2048)
    float* out = (float*)d_out;                   // (2048, 2048)

    u_gemm_kernel<<<dim3(N_RES / 64, T_STEPS / 64), 256>>>(input, w_in);
    esn_recur_kernel<<<GBLK, NTHREADS>>>(w_res, out);
}